// round 9
// baseline (speedup 1.0000x reference)
#include <cuda_runtime.h>
#include <math.h>

// Problem constants
#define D_MODEL 1024
#define D_FF    4096
#define BATCH   4
#define SEQ     2048
#define MROWS   (BATCH * SEQ)   // 8192

// ---------------------------------------------------------------------------
// Scratch (device globals; no dynamic allocation allowed). Aliased to keep
// the static footprint down:
//   g_xn : LN1 out, then LN2 out (xn2)
//   g_q  : Q, then ctx
//   g_k  : K, then x1 (= x + attn_out)
//   g_v  : V
//   g_s  : scores / probs
//   g_h  : relu(fc1)
// ---------------------------------------------------------------------------
__device__ float g_xn[MROWS * (size_t)D_MODEL];
__device__ float g_q [MROWS * (size_t)D_MODEL];
__device__ float g_k [MROWS * (size_t)D_MODEL];
__device__ float g_v [MROWS * (size_t)D_MODEL];
__device__ float g_s [(size_t)BATCH * SEQ * SEQ];
__device__ float g_h [MROWS * (size_t)D_FF];

// ---------------------------------------------------------------------------
// GEMM: C[M,N] = alpha * A[M,K] @ op(B)  (+bias[n]) (+relu) (+resid[m,n])
//   BNT  = true : B is [N,K] row-major ("NT", C = A @ B^T)
//   BNT  = false: B is [K,N] row-major ("NN")
//   EPI bit0 = bias, bit1 = relu, bit2 = residual add
//   CSKIP    = skip blocks strictly above the diagonal (causal scores)
//   CTRIM    = K loop only up to m0+BM (A columns beyond are zero: probs@v)
//   Batched via blockIdx.z with element strides sA/sB/sC (resid not batched).
// Double-buffered smem pipeline; 128x128 tile, BK=8, 8x8 micro-tile.
// All dims must be multiples of the tile sizes (true for this problem).
// ---------------------------------------------------------------------------
template<bool BNT, int EPI, bool CSKIP, bool CTRIM>
__global__ void __launch_bounds__(256, 2)
gemm128(const float* __restrict__ A, const float* __restrict__ B,
        float* __restrict__ C, const float* __restrict__ bias,
        const float* __restrict__ resid,
        int M, int N, int K, float alpha,
        long long sA, long long sB, long long sC)
{
    constexpr int BM = 128, BN = 128, BK = 8;
    const int m0 = blockIdx.y * BM;
    const int n0 = blockIdx.x * BN;
    if (CSKIP && n0 > m0) return;   // fully-masked tile: softmax never reads it

    const long long bz = blockIdx.z;
    A += bz * sA;
    B += bz * sB;
    C += bz * sC;

    __shared__ float As[2][BK][BM];
    __shared__ float Bs[2][BK][BN];

    const int tid   = threadIdx.x;
    const int ty    = tid >> 4;          // 0..15
    const int tx    = tid & 15;          // 0..15
    const int ldRow = tid >> 1;          // 0..127
    const int ldCol = (tid & 1) << 2;    // 0 or 4
    const int bK    = tid >> 5;          // 0..7   (NN load)
    const int bN    = (tid & 31) << 2;   // 0..124 (NN load)

    const float* aPtr = A + (long long)(m0 + ldRow) * K + ldCol;
    const float* bPtr = BNT ? (B + (long long)(n0 + ldRow) * K + ldCol)
                            : (B + (long long)bK * N + n0 + bN);

    const int kEnd = CTRIM ? (m0 + BM) : K;   // zero A-cols beyond m0+BM

    float acc[8][8];
    #pragma unroll
    for (int i = 0; i < 8; i++)
        #pragma unroll
        for (int j = 0; j < 8; j++) acc[i][j] = 0.f;

    auto ldA = [&](int k0) { return *(const float4*)(aPtr + k0); };
    auto ldB = [&](int k0) {
        return BNT ? *(const float4*)(bPtr + k0)
                   : *(const float4*)(bPtr + (long long)k0 * N);
    };
    auto stA = [&](int buf, float4 a4) {
        As[buf][ldCol + 0][ldRow] = a4.x;
        As[buf][ldCol + 1][ldRow] = a4.y;
        As[buf][ldCol + 2][ldRow] = a4.z;
        As[buf][ldCol + 3][ldRow] = a4.w;
    };
    auto stB = [&](int buf, float4 b4) {
        if (BNT) {
            Bs[buf][ldCol + 0][ldRow] = b4.x;
            Bs[buf][ldCol + 1][ldRow] = b4.y;
            Bs[buf][ldCol + 2][ldRow] = b4.z;
            Bs[buf][ldCol + 3][ldRow] = b4.w;
        } else {
            *(float4*)&Bs[buf][bK][bN] = b4;
        }
    };
    auto compute = [&](int buf) {
        #pragma unroll
        for (int kk = 0; kk < BK; kk++) {
            float4 ra0 = *(const float4*)&As[buf][kk][ty * 8];
            float4 ra1 = *(const float4*)&As[buf][kk][ty * 8 + 4];
            float4 rb0 = *(const float4*)&Bs[buf][kk][tx * 8];
            float4 rb1 = *(const float4*)&Bs[buf][kk][tx * 8 + 4];
            float ra[8] = {ra0.x, ra0.y, ra0.z, ra0.w, ra1.x, ra1.y, ra1.z, ra1.w};
            float rb[8] = {rb0.x, rb0.y, rb0.z, rb0.w, rb1.x, rb1.y, rb1.z, rb1.w};
            #pragma unroll
            for (int i = 0; i < 8; i++)
                #pragma unroll
                for (int j = 0; j < 8; j++)
                    acc[i][j] = fmaf(ra[i], rb[j], acc[i][j]);
        }
    };

    // Prologue: fill buffer 0
    {
        float4 a4 = ldA(0);
        float4 b4 = ldB(0);
        stA(0, a4);
        stB(0, b4);
    }
    __syncthreads();

    int buf = 0;
    for (int k0 = BK; k0 < kEnd; k0 += BK) {
        float4 a4 = ldA(k0);          // prefetch next tile (global)
        float4 b4 = ldB(k0);
        compute(buf);                 // compute on current buffer
        stA(buf ^ 1, a4);             // stage next buffer
        stB(buf ^ 1, b4);
        __syncthreads();
        buf ^= 1;
    }
    compute(buf);                     // epilogue tile

    #pragma unroll
    for (int i = 0; i < 8; i++) {
        const long long m = m0 + ty * 8 + i;
        #pragma unroll
        for (int j = 0; j < 8; j += 4) {
            const int n = n0 + tx * 8 + j;
            float4 v;
            v.x = acc[i][j + 0] * alpha;
            v.y = acc[i][j + 1] * alpha;
            v.z = acc[i][j + 2] * alpha;
            v.w = acc[i][j + 3] * alpha;
            if (EPI & 1) {
                float4 bb = *(const float4*)(bias + n);
                v.x += bb.x; v.y += bb.y; v.z += bb.z; v.w += bb.w;
            }
            if (EPI & 2) {
                v.x = fmaxf(v.x, 0.f); v.y = fmaxf(v.y, 0.f);
                v.z = fmaxf(v.z, 0.f); v.w = fmaxf(v.w, 0.f);
            }
            if (EPI & 4) {
                float4 rr = *(const float4*)(resid + m * N + n);
                v.x += rr.x; v.y += rr.y; v.z += rr.z; v.w += rr.w;
            }
            *(float4*)(C + m * N + n) = v;
        }
    }
}

// ---------------------------------------------------------------------------
// LayerNorm over last dim (1024). One block (256 threads) per row, float4.
// ---------------------------------------------------------------------------
__global__ void layernorm_kernel(const float* __restrict__ x,
                                 const float* __restrict__ g,
                                 const float* __restrict__ b,
                                 float* __restrict__ out)
{
    __shared__ float shs[8], shq[8];
    const size_t row = blockIdx.x;
    const int tid = threadIdx.x;  // 0..255, 4 floats each -> 1024

    float4 v = ((const float4*)(x + row * D_MODEL))[tid];
    float s = v.x + v.y + v.z + v.w;
    float q = v.x * v.x + v.y * v.y + v.z * v.z + v.w * v.w;

    #pragma unroll
    for (int o = 16; o > 0; o >>= 1) {
        s += __shfl_xor_sync(0xffffffffu, s, o);
        q += __shfl_xor_sync(0xffffffffu, q, o);
    }
    if ((tid & 31) == 0) { shs[tid >> 5] = s; shq[tid >> 5] = q; }
    __syncthreads();
    s = shs[tid & 7];
    q = shq[tid & 7];
    #pragma unroll
    for (int o = 4; o > 0; o >>= 1) {
        s += __shfl_xor_sync(0xffffffffu, s, o);
        q += __shfl_xor_sync(0xffffffffu, q, o);
    }

    const float mu  = s * (1.f / D_MODEL);
    const float var = q * (1.f / D_MODEL) - mu * mu;
    const float inv = rsqrtf(var + 1e-5f);

    float4 gg = ((const float4*)g)[tid];
    float4 bb = ((const float4*)b)[tid];
    float4 o4;
    o4.x = (v.x - mu) * inv * gg.x + bb.x;
    o4.y = (v.y - mu) * inv * gg.y + bb.y;
    o4.z = (v.z - mu) * inv * gg.z + bb.z;
    o4.w = (v.w - mu) * inv * gg.w + bb.w;
    ((float4*)(out + row * D_MODEL))[tid] = o4;
}

// ---------------------------------------------------------------------------
// Causal softmax in-place on scores [B*S, S]. One block per row.
// Masked tail (c > r) is written as 0 so the ctx GEMM can be dense.
// ---------------------------------------------------------------------------
__global__ void softmax_causal(float* __restrict__ Sc)
{
    __shared__ float sh[8];
    const size_t row = blockIdx.x;
    const int r   = (int)(row % SEQ);
    const int len = r + 1;
    float* p = Sc + row * (size_t)SEQ;
    const int tid = threadIdx.x;  // 256

    float mx = -3.0e38f;
    for (int c = tid; c < len; c += 256) mx = fmaxf(mx, p[c]);
    #pragma unroll
    for (int o = 16; o > 0; o >>= 1) mx = fmaxf(mx, __shfl_xor_sync(0xffffffffu, mx, o));
    if ((tid & 31) == 0) sh[tid >> 5] = mx;
    __syncthreads();
    mx = sh[tid & 7];
    #pragma unroll
    for (int o = 4; o > 0; o >>= 1) mx = fmaxf(mx, __shfl_xor_sync(0xffffffffu, mx, o));
    __syncthreads();

    float sum = 0.f;
    for (int c = tid; c < len; c += 256) {
        float e = expf(p[c] - mx);
        p[c] = e;
        sum += e;
    }
    #pragma unroll
    for (int o = 16; o > 0; o >>= 1) sum += __shfl_xor_sync(0xffffffffu, sum, o);
    if ((tid & 31) == 0) sh[tid >> 5] = sum;
    __syncthreads();
    sum = sh[tid & 7];
    #pragma unroll
    for (int o = 4; o > 0; o >>= 1) sum += __shfl_xor_sync(0xffffffffu, sum, o);

    const float inv = 1.f / sum;
    for (int c = tid; c < SEQ; c += 256)
        p[c] = (c < len) ? p[c] * inv : 0.f;
}

// ---------------------------------------------------------------------------
// Launch
// ---------------------------------------------------------------------------
extern "C" void kernel_launch(void* const* d_in, const int* in_sizes, int n_in,
                              void* d_out, int out_size)
{
    const float* x     = (const float*)d_in[0];
    const float* W_q   = (const float*)d_in[1];
    const float* W_k   = (const float*)d_in[2];
    const float* W_v   = (const float*)d_in[3];
    const float* W_o   = (const float*)d_in[4];
    const float* fc1_w = (const float*)d_in[5];
    const float* fc1_b = (const float*)d_in[6];
    const float* fc2_w = (const float*)d_in[7];
    const float* fc2_b = (const float*)d_in[8];
    const float* ln1_g = (const float*)d_in[9];
    const float* ln1_b = (const float*)d_in[10];
    const float* ln2_g = (const float*)d_in[11];
    const float* ln2_b = (const float*)d_in[12];
    float* out = (float*)d_out;

    float *xn, *q, *k, *v, *s, *h;
    cudaGetSymbolAddress((void**)&xn, g_xn);
    cudaGetSymbolAddress((void**)&q,  g_q);
    cudaGetSymbolAddress((void**)&k,  g_k);
    cudaGetSymbolAddress((void**)&v,  g_v);
    cudaGetSymbolAddress((void**)&s,  g_s);
    cudaGetSymbolAddress((void**)&h,  g_h);

    // Buffer aliases (lifetimes do not overlap)
    float* ctx = q;    // Q dead after scores
    float* x1  = k;    // K dead after scores
    float* xn2 = xn;   // LN1 out dead after QKV

    const long long sQK = (long long)SEQ * D_MODEL;   // per-batch q/k/v stride
    const long long sSS = (long long)SEQ * SEQ;       // per-batch scores stride

    // 1) LN1
    layernorm_kernel<<<MROWS, 256>>>(x, ln1_g, ln1_b, xn);

    // 2) Q, K, V = xn @ W^T   (M=8192, N=1024, K=1024)
    dim3 gD(D_MODEL / 128, MROWS / 128, 1);
    gemm128<true, 0, false, false><<<gD, 256>>>(xn, W_q, q, nullptr, nullptr,
                                                MROWS, D_MODEL, D_MODEL, 1.f, 0, 0, 0);
    gemm128<true, 0, false, false><<<gD, 256>>>(xn, W_k, k, nullptr, nullptr,
                                                MROWS, D_MODEL, D_MODEL, 1.f, 0, 0, 0);
    gemm128<true, 0, false, false><<<gD, 256>>>(xn, W_v, v, nullptr, nullptr,
                                                MROWS, D_MODEL, D_MODEL, 1.f, 0, 0, 0);

    // 3) scores = q @ k^T / 32   (batched, causal block-skip)
    dim3 gS(SEQ / 128, SEQ / 128, BATCH);
    gemm128<true, 0, true, false><<<gS, 256>>>(q, k, s, nullptr, nullptr,
                                               SEQ, SEQ, D_MODEL, 1.f / 32.f,
                                               sQK, sQK, sSS);

    // 4) causal softmax (writes zeros in masked tail)
    softmax_causal<<<MROWS, 256>>>(s);

    // 5) ctx = probs @ v   (batched NN, K trimmed to causal extent)
    dim3 gC(D_MODEL / 128, SEQ / 128, BATCH);
    gemm128<false, 0, false, true><<<gC, 256>>>(s, v, ctx, nullptr, nullptr,
                                                SEQ, D_MODEL, SEQ, 1.f,
                                                sSS, sQK, sQK);

    // 6) x1 = x + ctx @ W_o^T
    gemm128<true, 4, false, false><<<gD, 256>>>(ctx, W_o, x1, nullptr, x,
                                                MROWS, D_MODEL, D_MODEL, 1.f, 0, 0, 0);

    // 7) LN2
    layernorm_kernel<<<MROWS, 256>>>(x1, ln2_g, ln2_b, xn2);

    // 8) h = relu(xn2 @ fc1_w^T + fc1_b)   (M=8192, N=4096, K=1024)
    dim3 gF(D_FF / 128, MROWS / 128, 1);
    gemm128<true, 3, false, false><<<gF, 256>>>(xn2, fc1_w, h, fc1_b, nullptr,
                                                MROWS, D_FF, D_MODEL, 1.f, 0, 0, 0);

    // 9) out = x1 + h @ fc2_w^T + fc2_b   (M=8192, N=1024, K=4096)
    gemm128<true, 5, false, false><<<gD, 256>>>(h, fc2_w, out, fc2_b, x1,
                                                MROWS, D_MODEL, D_FF, 1.f, 0, 0, 0);
}

// round 11
// speedup vs baseline: 1.5607x; 1.5607x over previous
#include <cuda_runtime.h>
#include <math.h>
#include <stdint.h>

// Problem constants
#define D_MODEL 1024
#define D_FF    4096
#define BATCH   4
#define SEQ     2048
#define MROWS   (BATCH * SEQ)   // 8192

// ---------------------------------------------------------------------------
// Scratch (device globals; no dynamic allocation allowed). Aliased:
//   g_xn : LN1 out, then LN2 out          g_q : Q, then ctx
//   g_k  : K, then x1 (= x + attn_out)    g_v : V
//   g_s  : scores / probs                 g_h : relu(fc1)
// ---------------------------------------------------------------------------
__device__ float g_xn[MROWS * (size_t)D_MODEL];
__device__ float g_q [MROWS * (size_t)D_MODEL];
__device__ float g_k [MROWS * (size_t)D_MODEL];
__device__ float g_v [MROWS * (size_t)D_MODEL];
__device__ float g_s [(size_t)BATCH * SEQ * SEQ];
__device__ float g_h [MROWS * (size_t)D_FF];

// Round fp32 -> tf32 (round-to-nearest) kept in a 32-bit container.
__device__ __forceinline__ float to_tf32(float x) {
    uint32_t u;
    asm("cvt.rna.tf32.f32 %0, %1;" : "=r"(u) : "f"(x));
    return __uint_as_float(u);
}

__device__ __forceinline__ void mma_tf32(float c[4],
                                         const uint32_t a[4],
                                         const uint32_t b[2]) {
    asm volatile(
        "mma.sync.aligned.m16n8k8.row.col.f32.tf32.tf32.f32 "
        "{%0,%1,%2,%3}, {%4,%5,%6,%7}, {%8,%9}, {%0,%1,%2,%3};"
        : "+f"(c[0]), "+f"(c[1]), "+f"(c[2]), "+f"(c[3])
        : "r"(a[0]), "r"(a[1]), "r"(a[2]), "r"(a[3]),
          "r"(b[0]), "r"(b[1]));
}

// ---------------------------------------------------------------------------
// TF32 tensor-core GEMM: C[M,N] = alpha * A[M,K] @ op(B) (+bias)(+relu)(+resid)
//   BNT  = true : B is [N,K] row-major (C = A @ B^T);  false: B is [K,N]
//   EPI bit0 = bias, bit1 = relu, bit2 = residual add
//   CSKIP    = skip blocks strictly above the diagonal (causal scores)
//   CTRIM    = K loop only up to m0+BM (A cols beyond are zero: probs@v)
// 128x128x16 tile, double-buffered smem (tf32 values), 8 warps, each warp
// owns a 64x32 tile = 4x4 m16n8k8 MMAs per k8 step. All dims multiples of
// tile sizes (true here).
// ---------------------------------------------------------------------------
template<bool BNT, int EPI, bool CSKIP, bool CTRIM>
__global__ void __launch_bounds__(256, 2)
gemm_tc(const float* __restrict__ A, const float* __restrict__ B,
        float* __restrict__ C, const float* __restrict__ bias,
        const float* __restrict__ resid,
        int M, int N, int K, float alpha,
        long long sA, long long sB, long long sC)
{
    constexpr int BM = 128, BN = 128, BK = 16, LDA_ = BM + 8;  // pad 8: conflict-free
    const int m0 = blockIdx.y * BM;
    const int n0 = blockIdx.x * BN;
    if (CSKIP && n0 > m0) return;   // fully-masked tile

    A += blockIdx.z * sA;
    B += blockIdx.z * sB;
    C += blockIdx.z * sC;

    __shared__ float As[2][BK][LDA_];   // [k][m], tf32 values
    __shared__ float Bs[2][BK][LDA_];   // [k][n], tf32 values

    const int tid  = threadIdx.x;
    const int lane = tid & 31;
    const int wid  = tid >> 5;
    const int wm   = (wid >> 2) * 64;   // warp m offset in tile
    const int wn   = (wid & 3) * 32;    // warp n offset in tile
    const int lr   = lane >> 2;         // 0..7
    const int lc   = lane & 3;          // 0..3

    // Global-load mapping. A (and NT-B): one row per thread, k-quad by tid>>7;
    // all lanes of a warp share aCol -> STS to As[k][m] is conflict-free.
    const int aRow = tid & 127;
    const int aCol = (tid >> 7) << 2;   // 0 or 4 (second 8 k's via +8)
    // NN-B: straight [k][n] rows, coalesced.
    const int bKr = tid >> 5;           // 0..7
    const int bNc = (tid & 31) << 2;    // 0..124

    const float* aP = A + (long long)(m0 + aRow) * K + aCol;
    const float* bP = BNT ? (B + (long long)(n0 + aRow) * K + aCol)
                          : (B + (long long)bKr * N + n0 + bNc);

    const int kEnd = CTRIM ? (m0 + BM) : K;

    float acc[4][4][4];
    #pragma unroll
    for (int mi = 0; mi < 4; mi++)
        #pragma unroll
        for (int ni = 0; ni < 4; ni++)
            #pragma unroll
            for (int r = 0; r < 4; r++) acc[mi][ni][r] = 0.f;

    auto ldGA = [&](int k0, float4& x, float4& y) {
        x = *(const float4*)(aP + k0);
        y = *(const float4*)(aP + k0 + 8);
    };
    auto ldGB = [&](int k0, float4& x, float4& y) {
        if (BNT) {
            x = *(const float4*)(bP + k0);
            y = *(const float4*)(bP + k0 + 8);
        } else {
            x = *(const float4*)(bP + (long long)k0 * N);
            y = *(const float4*)(bP + (long long)(k0 + 8) * N);
        }
    };
    auto stS = [&](int buf, float4 ax, float4 ay, float4 bx, float4 by) {
        As[buf][aCol + 0][aRow] = to_tf32(ax.x);
        As[buf][aCol + 1][aRow] = to_tf32(ax.y);
        As[buf][aCol + 2][aRow] = to_tf32(ax.z);
        As[buf][aCol + 3][aRow] = to_tf32(ax.w);
        As[buf][aCol + 8][aRow] = to_tf32(ay.x);
        As[buf][aCol + 9][aRow] = to_tf32(ay.y);
        As[buf][aCol + 10][aRow] = to_tf32(ay.z);
        As[buf][aCol + 11][aRow] = to_tf32(ay.w);
        if (BNT) {
            Bs[buf][aCol + 0][aRow] = to_tf32(bx.x);
            Bs[buf][aCol + 1][aRow] = to_tf32(bx.y);
            Bs[buf][aCol + 2][aRow] = to_tf32(bx.z);
            Bs[buf][aCol + 3][aRow] = to_tf32(bx.w);
            Bs[buf][aCol + 8][aRow] = to_tf32(by.x);
            Bs[buf][aCol + 9][aRow] = to_tf32(by.y);
            Bs[buf][aCol + 10][aRow] = to_tf32(by.z);
            Bs[buf][aCol + 11][aRow] = to_tf32(by.w);
        } else {
            float4 t0 = make_float4(to_tf32(bx.x), to_tf32(bx.y),
                                    to_tf32(bx.z), to_tf32(bx.w));
            float4 t1 = make_float4(to_tf32(by.x), to_tf32(by.y),
                                    to_tf32(by.z), to_tf32(by.w));
            *(float4*)&Bs[buf][bKr][bNc]     = t0;
            *(float4*)&Bs[buf][bKr + 8][bNc] = t1;
        }
    };
    auto compute = [&](int buf) {
        #pragma unroll
        for (int kk = 0; kk < BK; kk += 8) {
            uint32_t af[4][4], bf[4][2];
            #pragma unroll
            for (int mi = 0; mi < 4; mi++) {
                const int rb = wm + mi * 16;
                af[mi][0] = __float_as_uint(As[buf][kk + lc][rb + lr]);
                af[mi][1] = __float_as_uint(As[buf][kk + lc][rb + lr + 8]);
                af[mi][2] = __float_as_uint(As[buf][kk + lc + 4][rb + lr]);
                af[mi][3] = __float_as_uint(As[buf][kk + lc + 4][rb + lr + 8]);
            }
            #pragma unroll
            for (int ni = 0; ni < 4; ni++) {
                const int nb = wn + ni * 8;
                bf[ni][0] = __float_as_uint(Bs[buf][kk + lc][nb + lr]);
                bf[ni][1] = __float_as_uint(Bs[buf][kk + lc + 4][nb + lr]);
            }
            #pragma unroll
            for (int mi = 0; mi < 4; mi++)
                #pragma unroll
                for (int ni = 0; ni < 4; ni++)
                    mma_tf32(acc[mi][ni], af[mi], bf[ni]);
        }
    };

    // Prologue: fill buffer 0
    {
        float4 ax, ay, bx, by;
        ldGA(0, ax, ay);
        ldGB(0, bx, by);
        stS(0, ax, ay, bx, by);
    }
    __syncthreads();

    int buf = 0;
    for (int k0 = BK; k0 < kEnd; k0 += BK) {
        float4 ax, ay, bx, by;
        ldGA(k0, ax, ay);              // prefetch next tile
        ldGB(k0, bx, by);
        compute(buf);                  // compute on current buffer
        stS(buf ^ 1, ax, ay, bx, by);  // stage next buffer
        __syncthreads();
        buf ^= 1;
    }
    compute(buf);

    // Epilogue: c0,c1 -> (row lr, cols 2*lc,2*lc+1); c2,c3 -> row lr+8
    #pragma unroll
    for (int mi = 0; mi < 4; mi++) {
        #pragma unroll
        for (int ni = 0; ni < 4; ni++) {
            const long long r0 = m0 + wm + mi * 16 + lr;
            const long long r1 = r0 + 8;
            const int cb = n0 + wn + ni * 8 + lc * 2;
            float2 v0, v1;
            v0.x = acc[mi][ni][0] * alpha;
            v0.y = acc[mi][ni][1] * alpha;
            v1.x = acc[mi][ni][2] * alpha;
            v1.y = acc[mi][ni][3] * alpha;
            if (EPI & 1) {
                float2 bb = *(const float2*)(bias + cb);
                v0.x += bb.x; v0.y += bb.y;
                v1.x += bb.x; v1.y += bb.y;
            }
            if (EPI & 2) {
                v0.x = fmaxf(v0.x, 0.f); v0.y = fmaxf(v0.y, 0.f);
                v1.x = fmaxf(v1.x, 0.f); v1.y = fmaxf(v1.y, 0.f);
            }
            if (EPI & 4) {
                float2 ra = *(const float2*)(resid + r0 * N + cb);
                float2 rb = *(const float2*)(resid + r1 * N + cb);
                v0.x += ra.x; v0.y += ra.y;
                v1.x += rb.x; v1.y += rb.y;
            }
            *(float2*)(C + r0 * N + cb) = v0;
            *(float2*)(C + r1 * N + cb) = v1;
        }
    }
}

// ---------------------------------------------------------------------------
// LayerNorm over last dim (1024). One block (256 threads) per row, float4.
// ---------------------------------------------------------------------------
__global__ void layernorm_kernel(const float* __restrict__ x,
                                 const float* __restrict__ g,
                                 const float* __restrict__ b,
                                 float* __restrict__ out)
{
    __shared__ float shs[8], shq[8];
    const size_t row = blockIdx.x;
    const int tid = threadIdx.x;

    float4 v = ((const float4*)(x + row * D_MODEL))[tid];
    float s = v.x + v.y + v.z + v.w;
    float q = v.x * v.x + v.y * v.y + v.z * v.z + v.w * v.w;

    #pragma unroll
    for (int o = 16; o > 0; o >>= 1) {
        s += __shfl_xor_sync(0xffffffffu, s, o);
        q += __shfl_xor_sync(0xffffffffu, q, o);
    }
    if ((tid & 31) == 0) { shs[tid >> 5] = s; shq[tid >> 5] = q; }
    __syncthreads();
    s = shs[tid & 7];
    q = shq[tid & 7];
    #pragma unroll
    for (int o = 4; o > 0; o >>= 1) {
        s += __shfl_xor_sync(0xffffffffu, s, o);
        q += __shfl_xor_sync(0xffffffffu, q, o);
    }

    const float mu  = s * (1.f / D_MODEL);
    const float var = q * (1.f / D_MODEL) - mu * mu;
    const float inv = rsqrtf(var + 1e-5f);

    float4 gg = ((const float4*)g)[tid];
    float4 bb = ((const float4*)b)[tid];
    float4 o4;
    o4.x = (v.x - mu) * inv * gg.x + bb.x;
    o4.y = (v.y - mu) * inv * gg.y + bb.y;
    o4.z = (v.z - mu) * inv * gg.z + bb.z;
    o4.w = (v.w - mu) * inv * gg.w + bb.w;
    ((float4*)(out + row * D_MODEL))[tid] = o4;
}

// ---------------------------------------------------------------------------
// Causal softmax in-place on scores [B*S, S]. One block per row.
// Masked tail (c > r) is written as 0 so the ctx GEMM can be dense.
// ---------------------------------------------------------------------------
__global__ void softmax_causal(float* __restrict__ Sc)
{
    __shared__ float sh[8];
    const size_t row = blockIdx.x;
    const int r   = (int)(row % SEQ);
    const int len = r + 1;
    float* p = Sc + row * (size_t)SEQ;
    const int tid = threadIdx.x;

    float mx = -3.0e38f;
    for (int c = tid; c < len; c += 256) mx = fmaxf(mx, p[c]);
    #pragma unroll
    for (int o = 16; o > 0; o >>= 1) mx = fmaxf(mx, __shfl_xor_sync(0xffffffffu, mx, o));
    if ((tid & 31) == 0) sh[tid >> 5] = mx;
    __syncthreads();
    mx = sh[tid & 7];
    #pragma unroll
    for (int o = 4; o > 0; o >>= 1) mx = fmaxf(mx, __shfl_xor_sync(0xffffffffu, mx, o));
    __syncthreads();

    float sum = 0.f;
    for (int c = tid; c < len; c += 256) {
        float e = expf(p[c] - mx);
        p[c] = e;
        sum += e;
    }
    #pragma unroll
    for (int o = 16; o > 0; o >>= 1) sum += __shfl_xor_sync(0xffffffffu, sum, o);
    if ((tid & 31) == 0) sh[tid >> 5] = sum;
    __syncthreads();
    sum = sh[tid & 7];
    #pragma unroll
    for (int o = 4; o > 0; o >>= 1) sum += __shfl_xor_sync(0xffffffffu, sum, o);

    const float inv = 1.f / sum;
    for (int c = tid; c < SEQ; c += 256)
        p[c] = (c < len) ? p[c] * inv : 0.f;
}

// ---------------------------------------------------------------------------
// Launch
// ---------------------------------------------------------------------------
extern "C" void kernel_launch(void* const* d_in, const int* in_sizes, int n_in,
                              void* d_out, int out_size)
{
    const float* x     = (const float*)d_in[0];
    const float* W_q   = (const float*)d_in[1];
    const float* W_k   = (const float*)d_in[2];
    const float* W_v   = (const float*)d_in[3];
    const float* W_o   = (const float*)d_in[4];
    const float* fc1_w = (const float*)d_in[5];
    const float* fc1_b = (const float*)d_in[6];
    const float* fc2_w = (const float*)d_in[7];
    const float* fc2_b = (const float*)d_in[8];
    const float* ln1_g = (const float*)d_in[9];
    const float* ln1_b = (const float*)d_in[10];
    const float* ln2_g = (const float*)d_in[11];
    const float* ln2_b = (const float*)d_in[12];
    float* out = (float*)d_out;

    float *xn, *q, *k, *v, *s, *h;
    cudaGetSymbolAddress((void**)&xn, g_xn);
    cudaGetSymbolAddress((void**)&q,  g_q);
    cudaGetSymbolAddress((void**)&k,  g_k);
    cudaGetSymbolAddress((void**)&v,  g_v);
    cudaGetSymbolAddress((void**)&s,  g_s);
    cudaGetSymbolAddress((void**)&h,  g_h);

    // Buffer aliases (lifetimes do not overlap)
    float* ctx = q;
    float* x1  = k;
    float* xn2 = xn;

    const long long sQK = (long long)SEQ * D_MODEL;
    const long long sSS = (long long)SEQ * SEQ;

    // 1) LN1
    layernorm_kernel<<<MROWS, 256>>>(x, ln1_g, ln1_b, xn);

    // 2) Q, K, V = xn @ W^T   (M=8192, N=1024, K=1024)
    dim3 gD(D_MODEL / 128, MROWS / 128, 1);
    gemm_tc<true, 0, false, false><<<gD, 256>>>(xn, W_q, q, nullptr, nullptr,
                                                MROWS, D_MODEL, D_MODEL, 1.f, 0, 0, 0);
    gemm_tc<true, 0, false, false><<<gD, 256>>>(xn, W_k, k, nullptr, nullptr,
                                                MROWS, D_MODEL, D_MODEL, 1.f, 0, 0, 0);
    gemm_tc<true, 0, false, false><<<gD, 256>>>(xn, W_v, v, nullptr, nullptr,
                                                MROWS, D_MODEL, D_MODEL, 1.f, 0, 0, 0);

    // 3) scores = q @ k^T / 32   (batched, causal block-skip)
    dim3 gS(SEQ / 128, SEQ / 128, BATCH);
    gemm_tc<true, 0, true, false><<<gS, 256>>>(q, k, s, nullptr, nullptr,
                                               SEQ, SEQ, D_MODEL, 1.f / 32.f,
                                               sQK, sQK, sSS);

    // 4) causal softmax (zero-fills masked tail)
    softmax_causal<<<MROWS, 256>>>(s);

    // 5) ctx = probs @ v   (batched NN, K trimmed to causal extent)
    dim3 gC(D_MODEL / 128, SEQ / 128, BATCH);
    gemm_tc<false, 0, false, true><<<gC, 256>>>(s, v, ctx, nullptr, nullptr,
                                                SEQ, D_MODEL, SEQ, 1.f,
                                                sSS, sQK, sQK);

    // 6) x1 = x + ctx @ W_o^T
    gemm_tc<true, 4, false, false><<<gD, 256>>>(ctx, W_o, x1, nullptr, x,
                                                MROWS, D_MODEL, D_MODEL, 1.f, 0, 0, 0);

    // 7) LN2
    layernorm_kernel<<<MROWS, 256>>>(x1, ln2_g, ln2_b, xn2);

    // 8) h = relu(xn2 @ fc1_w^T + fc1_b)   (M=8192, N=4096, K=1024)
    dim3 gF(D_FF / 128, MROWS / 128, 1);
    gemm_tc<true, 3, false, false><<<gF, 256>>>(xn2, fc1_w, h, fc1_b, nullptr,
                                                MROWS, D_FF, D_MODEL, 1.f, 0, 0, 0);

    // 9) out = x1 + h @ fc2_w^T + fc2_b   (M=8192, N=1024, K=4096)
    gemm_tc<true, 5, false, false><<<gD, 256>>>(h, fc2_w, out, fc2_b, x1,
                                                MROWS, D_MODEL, D_FF, 1.f, 0, 0, 0);
}

// round 14
// speedup vs baseline: 2.7259x; 1.7465x over previous
#include <cuda_runtime.h>
#include <math.h>
#include <stdint.h>

// Problem constants
#define D_MODEL 1024
#define D_FF    4096
#define BATCH   4
#define SEQ     2048
#define MROWS   (BATCH * SEQ)   // 8192

// ---------------------------------------------------------------------------
// Scratch (device globals). Aliased:
//   g_xn : LN1 out, then LN2 out          g_q : Q, then ctx
//   g_k  : K, then x1 (= x + attn_out)    g_v : V
//   g_s  : scores / probs                 g_h : relu(fc1)
// ---------------------------------------------------------------------------
__device__ float g_xn[MROWS * (size_t)D_MODEL];
__device__ float g_q [MROWS * (size_t)D_MODEL];
__device__ float g_k [MROWS * (size_t)D_MODEL];
__device__ float g_v [MROWS * (size_t)D_MODEL];
__device__ float g_s [(size_t)BATCH * SEQ * SEQ];
__device__ float g_h [MROWS * (size_t)D_FF];

__device__ __forceinline__ void cpa16(uint32_t s, const void* g) {
    asm volatile("cp.async.cg.shared.global [%0], [%1], 16;" :: "r"(s), "l"(g));
}
__device__ __forceinline__ void cpa_commit() {
    asm volatile("cp.async.commit_group;");
}
template<int N>
__device__ __forceinline__ void cpa_wait() {
    asm volatile("cp.async.wait_group %0;" :: "n"(N));
}

// m16n8k8 tf32 MMA. fp32 operands: HW truncates mantissa to tf32.
__device__ __forceinline__ void mma_tf32(float c[4],
                                         const uint32_t a[4],
                                         const uint32_t b[2]) {
    asm volatile(
        "mma.sync.aligned.m16n8k8.row.col.f32.tf32.tf32.f32 "
        "{%0,%1,%2,%3}, {%4,%5,%6,%7}, {%8,%9}, {%0,%1,%2,%3};"
        : "+f"(c[0]), "+f"(c[1]), "+f"(c[2]), "+f"(c[3])
        : "r"(a[0]), "r"(a[1]), "r"(a[2]), "r"(a[3]),
          "r"(b[0]), "r"(b[1]));
}

// ---------------------------------------------------------------------------
// TF32 tensor-core GEMM, cp.async 4-stage pipeline.
//   C[M,N] = alpha * A[M,K] @ op(B)  (+bias)(+relu)(+resid)
//   BNT true: B is [N,K] (C = A@B^T); false: B is [K,N]
//   EPI bit0 bias, bit1 relu, bit2 residual
//   CSKIP: skip blocks above diagonal (causal scores)
//   CTRIM: K loop to m0+BM only (probs@v causal trim)
// 128x128x16 tile, 8 warps x (64x32 warp tile) = 4x4 m16n8k8 per k8 step.
// Smem layouts (conflict-free fragment LDS):
//   As [m][k]  stride 20   (16+4 pad; 20*lr+lc covers all banks)
//   Bs NT [n][k] stride 20; Bs NN [k][n] stride 136 (128+8)
// Dynamic smem; launcher sets the attribute.
// ---------------------------------------------------------------------------
template<bool BNT, int EPI, bool CSKIP, bool CTRIM>
__global__ void __launch_bounds__(256, 2)
gemm_tc(const float* __restrict__ A, const float* __restrict__ B,
        float* __restrict__ C, const float* __restrict__ bias,
        const float* __restrict__ resid,
        int M, int N, int K, float alpha,
        long long sA, long long sB, long long sC)
{
    constexpr int BM = 128, BN = 128, BK = 16, STAGES = 4;
    constexpr int LDAS = BK + 4;               // 20
    constexpr int LDNN = BN + 8;               // 136
    constexpr int ASZ  = BM * LDAS;            // 2560 floats
    constexpr int BSZ  = BNT ? BN * LDAS : BK * LDNN;

    const int m0 = blockIdx.y * BM;
    const int n0 = blockIdx.x * BN;
    if (CSKIP && n0 > m0) return;

    A += blockIdx.z * sA;
    B += blockIdx.z * sB;
    C += blockIdx.z * sC;

    extern __shared__ float sm[];
    float* As = sm;                     // [STAGES][ASZ]
    float* Bs = sm + STAGES * ASZ;      // [STAGES][BSZ]
    const uint32_t sAu = (uint32_t)__cvta_generic_to_shared(As);
    const uint32_t sBu = (uint32_t)__cvta_generic_to_shared(Bs);

    const int tid  = threadIdx.x;
    const int lane = tid & 31;
    const int wid  = tid >> 5;
    const int wm   = (wid >> 2) * 64;
    const int wn   = (wid & 3) * 32;
    const int lr   = lane >> 2;          // 0..7
    const int lc   = lane & 3;           // 0..3

    // cp.async mappings
    const int aRow = tid >> 1;           // 0..127 (A rows / NT-B rows)
    const int aKc  = (tid & 1) * 8;      // 0 or 8
    const int bRow = tid >> 5;           // 0..7   (NN-B k rows; +8 second)
    const int bNc  = (tid & 31) * 4;     // 0..124

    const float* aG = A + (long long)(m0 + aRow) * K + aKc;
    const float* bG = BNT ? (B + (long long)(n0 + aRow) * K + aKc)
                          : (B + (long long)bRow * N + n0 + bNc);

    const int kEnd   = CTRIM ? (m0 + BM) : K;
    const int ktiles = kEnd / BK;

    auto load_tile = [&](int st, int tile) {
        {
            const float* g = aG + (long long)tile * BK;
            uint32_t d = sAu + (uint32_t)(st * ASZ + aRow * LDAS + aKc) * 4u;
            cpa16(d, g);
            cpa16(d + 16u, g + 4);
        }
        if (BNT) {
            const float* g = bG + (long long)tile * BK;
            uint32_t d = sBu + (uint32_t)(st * BSZ + aRow * LDAS + aKc) * 4u;
            cpa16(d, g);
            cpa16(d + 16u, g + 4);
        } else {
            const float* g = bG + (long long)tile * BK * N;
            uint32_t d = sBu + (uint32_t)(st * BSZ + bRow * LDNN + bNc) * 4u;
            cpa16(d, g);
            cpa16(d + (uint32_t)(8 * LDNN * 4), g + 8LL * N);
        }
    };

    float acc[4][4][4];
    #pragma unroll
    for (int mi = 0; mi < 4; mi++)
        #pragma unroll
        for (int ni = 0; ni < 4; ni++)
            #pragma unroll
            for (int r = 0; r < 4; r++) acc[mi][ni][r] = 0.f;

    auto compute = [&](int buf) {
        const float* as = As + buf * ASZ;
        const float* bs = Bs + buf * BSZ;
        #pragma unroll
        for (int kk = 0; kk < BK; kk += 8) {
            uint32_t af[4][4], bf[4][2];
            #pragma unroll
            for (int mi = 0; mi < 4; mi++) {
                const int r0 = (wm + mi * 16 + lr) * LDAS;
                const int r8 = r0 + 8 * LDAS;
                af[mi][0] = __float_as_uint(as[r0 + kk + lc]);
                af[mi][1] = __float_as_uint(as[r8 + kk + lc]);
                af[mi][2] = __float_as_uint(as[r0 + kk + lc + 4]);
                af[mi][3] = __float_as_uint(as[r8 + kk + lc + 4]);
            }
            #pragma unroll
            for (int ni = 0; ni < 4; ni++) {
                const int nb = wn + ni * 8 + lr;
                if (BNT) {
                    bf[ni][0] = __float_as_uint(bs[nb * LDAS + kk + lc]);
                    bf[ni][1] = __float_as_uint(bs[nb * LDAS + kk + lc + 4]);
                } else {
                    bf[ni][0] = __float_as_uint(bs[(kk + lc) * LDNN + nb]);
                    bf[ni][1] = __float_as_uint(bs[(kk + lc + 4) * LDNN + nb]);
                }
            }
            #pragma unroll
            for (int mi = 0; mi < 4; mi++)
                #pragma unroll
                for (int ni = 0; ni < 4; ni++)
                    mma_tf32(acc[mi][ni], af[mi], bf[ni]);
        }
    };

    // Prologue: put STAGES-1 tile-loads in flight.
    #pragma unroll
    for (int s = 0; s < STAGES - 1; s++) {
        if (s < ktiles) load_tile(s, s);
        cpa_commit();
    }

    for (int i = 0; i < ktiles; i++) {
        cpa_wait<STAGES - 2>();     // tile i landed
        __syncthreads();            // all warps done with buffer (i+3)%4's prior use
        const int nt = i + STAGES - 1;
        if (nt < ktiles) load_tile(nt % STAGES, nt);
        cpa_commit();
        compute(i % STAGES);
    }

    // Epilogue
    #pragma unroll
    for (int mi = 0; mi < 4; mi++) {
        #pragma unroll
        for (int ni = 0; ni < 4; ni++) {
            const long long r0 = m0 + wm + mi * 16 + lr;
            const long long r1 = r0 + 8;
            const int cb = n0 + wn + ni * 8 + lc * 2;
            float2 v0, v1;
            v0.x = acc[mi][ni][0] * alpha;
            v0.y = acc[mi][ni][1] * alpha;
            v1.x = acc[mi][ni][2] * alpha;
            v1.y = acc[mi][ni][3] * alpha;
            if (EPI & 1) {
                float2 bb = *(const float2*)(bias + cb);
                v0.x += bb.x; v0.y += bb.y;
                v1.x += bb.x; v1.y += bb.y;
            }
            if (EPI & 2) {
                v0.x = fmaxf(v0.x, 0.f); v0.y = fmaxf(v0.y, 0.f);
                v1.x = fmaxf(v1.x, 0.f); v1.y = fmaxf(v1.y, 0.f);
            }
            if (EPI & 4) {
                float2 ra = *(const float2*)(resid + r0 * N + cb);
                float2 rb = *(const float2*)(resid + r1 * N + cb);
                v0.x += ra.x; v0.y += ra.y;
                v1.x += rb.x; v1.y += rb.y;
            }
            *(float2*)(C + r0 * N + cb) = v0;
            *(float2*)(C + r1 * N + cb) = v1;
        }
    }
}

// ---------------------------------------------------------------------------
// LayerNorm over last dim (1024). One block (256 threads) per row, float4.
// ---------------------------------------------------------------------------
__global__ void layernorm_kernel(const float* __restrict__ x,
                                 const float* __restrict__ g,
                                 const float* __restrict__ b,
                                 float* __restrict__ out)
{
    __shared__ float shs[8], shq[8];
    const size_t row = blockIdx.x;
    const int tid = threadIdx.x;

    float4 v = ((const float4*)(x + row * D_MODEL))[tid];
    float s = v.x + v.y + v.z + v.w;
    float q = v.x * v.x + v.y * v.y + v.z * v.z + v.w * v.w;

    #pragma unroll
    for (int o = 16; o > 0; o >>= 1) {
        s += __shfl_xor_sync(0xffffffffu, s, o);
        q += __shfl_xor_sync(0xffffffffu, q, o);
    }
    if ((tid & 31) == 0) { shs[tid >> 5] = s; shq[tid >> 5] = q; }
    __syncthreads();
    s = shs[tid & 7];
    q = shq[tid & 7];
    #pragma unroll
    for (int o = 4; o > 0; o >>= 1) {
        s += __shfl_xor_sync(0xffffffffu, s, o);
        q += __shfl_xor_sync(0xffffffffu, q, o);
    }

    const float mu  = s * (1.f / D_MODEL);
    const float var = q * (1.f / D_MODEL) - mu * mu;
    const float inv = rsqrtf(var + 1e-5f);

    float4 gg = ((const float4*)g)[tid];
    float4 bb = ((const float4*)b)[tid];
    float4 o4;
    o4.x = (v.x - mu) * inv * gg.x + bb.x;
    o4.y = (v.y - mu) * inv * gg.y + bb.y;
    o4.z = (v.z - mu) * inv * gg.z + bb.z;
    o4.w = (v.w - mu) * inv * gg.w + bb.w;
    ((float4*)(out + row * D_MODEL))[tid] = o4;
}

// ---------------------------------------------------------------------------
// Causal softmax in-place on scores [B*S, S]. One block per row.
// Masked tail (c > r) written as 0 so the ctx GEMM can be dense.
// ---------------------------------------------------------------------------
__global__ void softmax_causal(float* __restrict__ Sc)
{
    __shared__ float sh[8];
    const size_t row = blockIdx.x;
    const int r   = (int)(row % SEQ);
    const int len = r + 1;
    float* p = Sc + row * (size_t)SEQ;
    const int tid = threadIdx.x;

    float mx = -3.0e38f;
    for (int c = tid; c < len; c += 256) mx = fmaxf(mx, p[c]);
    #pragma unroll
    for (int o = 16; o > 0; o >>= 1) mx = fmaxf(mx, __shfl_xor_sync(0xffffffffu, mx, o));
    if ((tid & 31) == 0) sh[tid >> 5] = mx;
    __syncthreads();
    mx = sh[tid & 7];
    #pragma unroll
    for (int o = 4; o > 0; o >>= 1) mx = fmaxf(mx, __shfl_xor_sync(0xffffffffu, mx, o));
    __syncthreads();

    float sum = 0.f;
    for (int c = tid; c < len; c += 256) {
        float e = expf(p[c] - mx);
        p[c] = e;
        sum += e;
    }
    #pragma unroll
    for (int o = 16; o > 0; o >>= 1) sum += __shfl_xor_sync(0xffffffffu, sum, o);
    if ((tid & 31) == 0) sh[tid >> 5] = sum;
    __syncthreads();
    sum = sh[tid & 7];
    #pragma unroll
    for (int o = 4; o > 0; o >>= 1) sum += __shfl_xor_sync(0xffffffffu, sum, o);

    const float inv = 1.f / sum;
    for (int c = tid; c < SEQ; c += 256)
        p[c] = (c < len) ? p[c] * inv : 0.f;
}

// ---------------------------------------------------------------------------
// Launch
// ---------------------------------------------------------------------------
extern "C" void kernel_launch(void* const* d_in, const int* in_sizes, int n_in,
                              void* d_out, int out_size)
{
    const float* x     = (const float*)d_in[0];
    const float* W_q   = (const float*)d_in[1];
    const float* W_k   = (const float*)d_in[2];
    const float* W_v   = (const float*)d_in[3];
    const float* W_o   = (const float*)d_in[4];
    const float* fc1_w = (const float*)d_in[5];
    const float* fc1_b = (const float*)d_in[6];
    const float* fc2_w = (const float*)d_in[7];
    const float* fc2_b = (const float*)d_in[8];
    const float* ln1_g = (const float*)d_in[9];
    const float* ln1_b = (const float*)d_in[10];
    const float* ln2_g = (const float*)d_in[11];
    const float* ln2_b = (const float*)d_in[12];
    float* out = (float*)d_out;

    float *xn, *q, *k, *v, *s, *h;
    cudaGetSymbolAddress((void**)&xn, g_xn);
    cudaGetSymbolAddress((void**)&q,  g_q);
    cudaGetSymbolAddress((void**)&k,  g_k);
    cudaGetSymbolAddress((void**)&v,  g_v);
    cudaGetSymbolAddress((void**)&s,  g_s);
    cudaGetSymbolAddress((void**)&h,  g_h);

    float* ctx = q;
    float* x1  = k;
    float* xn2 = xn;

    // Dynamic smem sizes (STAGES=4)
    const int SMEM_NT = 4 * (2560 + 2560) * 4;   // 81920 B
    const int SMEM_NN = 4 * (2560 + 16 * 136) * 4; // 75776 B
    cudaFuncSetAttribute(gemm_tc<true, 0, false, false>,
                         cudaFuncAttributeMaxDynamicSharedMemorySize, SMEM_NT);
    cudaFuncSetAttribute(gemm_tc<true, 0, true, false>,
                         cudaFuncAttributeMaxDynamicSharedMemorySize, SMEM_NT);
    cudaFuncSetAttribute(gemm_tc<false, 0, false, true>,
                         cudaFuncAttributeMaxDynamicSharedMemorySize, SMEM_NN);
    cudaFuncSetAttribute(gemm_tc<true, 4, false, false>,
                         cudaFuncAttributeMaxDynamicSharedMemorySize, SMEM_NT);
    cudaFuncSetAttribute(gemm_tc<true, 3, false, false>,
                         cudaFuncAttributeMaxDynamicSharedMemorySize, SMEM_NT);
    cudaFuncSetAttribute(gemm_tc<true, 5, false, false>,
                         cudaFuncAttributeMaxDynamicSharedMemorySize, SMEM_NT);

    const long long sQK = (long long)SEQ * D_MODEL;
    const long long sSS = (long long)SEQ * SEQ;

    // 1) LN1
    layernorm_kernel<<<MROWS, 256>>>(x, ln1_g, ln1_b, xn);

    // 2) Q, K, V = xn @ W^T
    dim3 gD(D_MODEL / 128, MROWS / 128, 1);
    gemm_tc<true, 0, false, false><<<gD, 256, SMEM_NT>>>(xn, W_q, q, nullptr, nullptr,
                                                MROWS, D_MODEL, D_MODEL, 1.f, 0, 0, 0);
    gemm_tc<true, 0, false, false><<<gD, 256, SMEM_NT>>>(xn, W_k, k, nullptr, nullptr,
                                                MROWS, D_MODEL, D_MODEL, 1.f, 0, 0, 0);
    gemm_tc<true, 0, false, false><<<gD, 256, SMEM_NT>>>(xn, W_v, v, nullptr, nullptr,
                                                MROWS, D_MODEL, D_MODEL, 1.f, 0, 0, 0);

    // 3) scores = q @ k^T / 32  (batched, causal block-skip)
    dim3 gS(SEQ / 128, SEQ / 128, BATCH);
    gemm_tc<true, 0, true, false><<<gS, 256, SMEM_NT>>>(q, k, s, nullptr, nullptr,
                                               SEQ, SEQ, D_MODEL, 1.f / 32.f,
                                               sQK, sQK, sSS);

    // 4) causal softmax
    softmax_causal<<<MROWS, 256>>>(s);

    // 5) ctx = probs @ v  (batched NN, K trimmed)
    dim3 gC(D_MODEL / 128, SEQ / 128, BATCH);
    gemm_tc<false, 0, false, true><<<gC, 256, SMEM_NN>>>(s, v, ctx, nullptr, nullptr,
                                                SEQ, D_MODEL, SEQ, 1.f,
                                                sSS, sQK, sQK);

    // 6) x1 = x + ctx @ W_o^T
    gemm_tc<true, 4, false, false><<<gD, 256, SMEM_NT>>>(ctx, W_o, x1, nullptr, x,
                                                MROWS, D_MODEL, D_MODEL, 1.f, 0, 0, 0);

    // 7) LN2
    layernorm_kernel<<<MROWS, 256>>>(x1, ln2_g, ln2_b, xn2);

    // 8) h = relu(xn2 @ fc1_w^T + fc1_b)
    dim3 gF(D_FF / 128, MROWS / 128, 1);
    gemm_tc<true, 3, false, false><<<gF, 256, SMEM_NT>>>(xn2, fc1_w, h, fc1_b, nullptr,
                                                MROWS, D_FF, D_MODEL, 1.f, 0, 0, 0);

    // 9) out = x1 + h @ fc2_w^T + fc2_b
    gemm_tc<true, 5, false, false><<<gD, 256, SMEM_NT>>>(h, fc2_w, out, fc2_b, x1,
                                                MROWS, D_MODEL, D_FF, 1.f, 0, 0, 0);
}